// round 4
// baseline (speedup 1.0000x reference)
#include <cuda_runtime.h>
#include <cstddef>

#define N_NODES 50000
#define N_EDGES 1600000
#define D_FEAT  512
#define FILTERS 256
#define NCLS    16

// ---------------- device scratch (no allocations allowed) ----------------
__device__ float g_xw1[(size_t)N_NODES * FILTERS];   // X @ W1
__device__ float g_h  [(size_t)N_NODES * FILTERS];   // relu(A @ XW1)
__device__ float g_g  [(size_t)N_NODES * NCLS];      // H @ W2
__device__ int   g_deg[N_NODES];
__device__ int   g_rowptr[N_NODES + 1];
__device__ int   g_cursor[N_NODES];
__device__ int   g_csrc[N_EDGES];
__device__ float g_csw [N_EDGES];

// ---------------- CSR build ----------------
__global__ void k_zero_deg() {
    int i = blockIdx.x * 256 + threadIdx.x;
    if (i < N_NODES) g_deg[i] = 0;
}

__global__ void k_count(const int* __restrict__ dst) {
    int e = blockIdx.x * 256 + threadIdx.x;
    if (e < N_EDGES) atomicAdd(&g_deg[dst[e]], 1);
}

// Single-block exclusive scan over g_deg -> g_rowptr / g_cursor.
__global__ void k_scan() {
    __shared__ int sbuf[1024];
    int t = threadIdx.x;
    int carry = 0;
    for (int base = 0; base < N_NODES; base += 1024) {
        int v = (base + t < N_NODES) ? g_deg[base + t] : 0;
        sbuf[t] = v;
        __syncthreads();
        #pragma unroll
        for (int off = 1; off < 1024; off <<= 1) {
            int add = (t >= off) ? sbuf[t - off] : 0;
            __syncthreads();
            sbuf[t] += add;
            __syncthreads();
        }
        int excl = sbuf[t] - v + carry;   // exclusive prefix
        if (base + t < N_NODES) {
            g_rowptr[base + t] = excl;
            g_cursor[base + t] = excl;
        }
        int total = sbuf[1023];
        __syncthreads();                  // all reads of sbuf done before next chunk
        carry += total;
    }
    if (t == 0) g_rowptr[N_NODES] = carry;  // == N_EDGES
}

__global__ void k_scatter(const int* __restrict__ src, const int* __restrict__ dst,
                          const float* __restrict__ w) {
    int e = blockIdx.x * 256 + threadIdx.x;
    if (e < N_EDGES) {
        int d = dst[e];
        int pos = atomicAdd(&g_cursor[d], 1);
        g_csrc[pos] = src[e];
        g_csw [pos] = w[e];
    }
}

// ---------------- GEMM1: [50000,512] @ [512,256] fp32, packed f32x2 FMA ----------------
#define BM 128
#define BN 128
#define BK 16

union U2F4 { float4 f4; unsigned long long u2[2]; };

__device__ __forceinline__ unsigned long long pack2(float x) {
    unsigned long long r;
    unsigned int xi = __float_as_uint(x);
    asm("mov.b64 %0, {%1, %1};" : "=l"(r) : "r"(xi));
    return r;
}
__device__ __forceinline__ void ffma2(unsigned long long& d,
                                      unsigned long long a, unsigned long long b) {
    asm("fma.rn.f32x2 %0, %1, %2, %0;" : "+l"(d) : "l"(a), "l"(b));
}

__global__ __launch_bounds__(256) void k_gemm1(const float* __restrict__ A,
                                               const float* __restrict__ B) {
    __shared__ __align__(16) float As[BK][BM + 4];
    __shared__ __align__(16) float Bs[BK][BN];
    int t  = threadIdx.x;
    int tx = t & 15, ty = t >> 4;
    int bm = blockIdx.x * BM;
    int bn = blockIdx.y * BN;

    unsigned long long acc[8][4];
    #pragma unroll
    for (int m = 0; m < 8; m++)
        #pragma unroll
        for (int j = 0; j < 4; j++) acc[m][j] = 0ull;

    for (int k0 = 0; k0 < D_FEAT; k0 += BK) {
        // stage A (transpose to [k][m])
        #pragma unroll
        for (int i = 0; i < 2; i++) {
            int idx = t + i * 256;
            int row = idx >> 2;
            int kg  = (idx & 3) << 2;
            float4 v = make_float4(0.f, 0.f, 0.f, 0.f);
            int gr = bm + row;
            if (gr < N_NODES)
                v = *(const float4*)(A + (size_t)gr * D_FEAT + k0 + kg);
            As[kg + 0][row] = v.x; As[kg + 1][row] = v.y;
            As[kg + 2][row] = v.z; As[kg + 3][row] = v.w;
        }
        // stage B
        #pragma unroll
        for (int i = 0; i < 2; i++) {
            int idx = t + i * 256;
            int kr  = idx >> 5;
            int col = (idx & 31) << 2;
            *(float4*)&Bs[kr][col] =
                *(const float4*)(B + (size_t)(k0 + kr) * FILTERS + bn + col);
        }
        __syncthreads();
        #pragma unroll
        for (int kk = 0; kk < BK; kk++) {
            float4 a0 = *(const float4*)&As[kk][ty << 2];
            float4 a1 = *(const float4*)&As[kk][64 + (ty << 2)];
            U2F4 b0, b1;
            b0.f4 = *(const float4*)&Bs[kk][tx << 2];
            b1.f4 = *(const float4*)&Bs[kk][64 + (tx << 2)];
            float am[8] = {a0.x, a0.y, a0.z, a0.w, a1.x, a1.y, a1.z, a1.w};
            #pragma unroll
            for (int m = 0; m < 8; m++) {
                unsigned long long ap = pack2(am[m]);
                ffma2(acc[m][0], ap, b0.u2[0]);
                ffma2(acc[m][1], ap, b0.u2[1]);
                ffma2(acc[m][2], ap, b1.u2[0]);
                ffma2(acc[m][3], ap, b1.u2[1]);
            }
        }
        __syncthreads();
    }
    // epilogue
    #pragma unroll
    for (int m = 0; m < 8; m++) {
        int row = bm + ((m < 4) ? ((ty << 2) + m) : (64 + (ty << 2) + m - 4));
        if (row >= N_NODES) continue;
        U2F4 o0, o1;
        o0.u2[0] = acc[m][0]; o0.u2[1] = acc[m][1];
        o1.u2[0] = acc[m][2]; o1.u2[1] = acc[m][3];
        float* out = g_xw1 + (size_t)row * FILTERS + bn;
        *(float4*)(out + (tx << 2))      = o0.f4;
        *(float4*)(out + 64 + (tx << 2)) = o1.f4;
    }
}

// ---------------- Propagate 1 + relu: per-dst CSR, 64 threads/node, float4 ----------------
__global__ __launch_bounds__(256) void k_prop1() {
    int node = blockIdx.x * 4 + (threadIdx.x >> 6);
    int f = (threadIdx.x & 63) << 2;
    int s = g_rowptr[node], e = g_rowptr[node + 1];
    float4 acc = make_float4(0.f, 0.f, 0.f, 0.f);
    int i = s;
    for (; i + 1 < e; i += 2) {
        int   s0 = g_csrc[i],   s1 = g_csrc[i + 1];
        float w0 = g_csw[i],    w1 = g_csw[i + 1];
        float4 v0 = *(const float4*)(g_xw1 + (size_t)s0 * FILTERS + f);
        float4 v1 = *(const float4*)(g_xw1 + (size_t)s1 * FILTERS + f);
        acc.x = fmaf(w0, v0.x, acc.x); acc.y = fmaf(w0, v0.y, acc.y);
        acc.z = fmaf(w0, v0.z, acc.z); acc.w = fmaf(w0, v0.w, acc.w);
        acc.x = fmaf(w1, v1.x, acc.x); acc.y = fmaf(w1, v1.y, acc.y);
        acc.z = fmaf(w1, v1.z, acc.z); acc.w = fmaf(w1, v1.w, acc.w);
    }
    if (i < e) {
        int   s0 = g_csrc[i];
        float w0 = g_csw[i];
        float4 v0 = *(const float4*)(g_xw1 + (size_t)s0 * FILTERS + f);
        acc.x = fmaf(w0, v0.x, acc.x); acc.y = fmaf(w0, v0.y, acc.y);
        acc.z = fmaf(w0, v0.z, acc.z); acc.w = fmaf(w0, v0.w, acc.w);
    }
    float4 r = make_float4(fmaxf(acc.x, 0.f), fmaxf(acc.y, 0.f),
                           fmaxf(acc.z, 0.f), fmaxf(acc.w, 0.f));
    *(float4*)(g_h + (size_t)node * FILTERS + f) = r;
}

// ---------------- GEMM2: H[50000,256] @ W2[256,16] ----------------
__global__ __launch_bounds__(256) void k_gemm2(const float* __restrict__ W2) {
    __shared__ float Ht[32][FILTERS];          // 32 KB
    __shared__ float W2s[FILTERS][NCLS];       // 16 KB  (total exactly 48 KB)
    int t = threadIdx.x;
    #pragma unroll
    for (int i = 0; i < 16; i++)
        ((float*)W2s)[t + i * 256] = W2[t + i * 256];
    int base = blockIdx.x * 32;
    #pragma unroll
    for (int i = 0; i < 8; i++) {
        int idx = t + i * 256;
        int r = idx >> 6;
        int c4 = (idx & 63) << 2;
        int gr = base + r;
        float4 v = make_float4(0.f, 0.f, 0.f, 0.f);
        if (gr < N_NODES) v = *(const float4*)(g_h + (size_t)gr * FILTERS + c4);
        *(float4*)&Ht[r][c4] = v;
    }
    __syncthreads();
    int c = t & 15, r0 = t >> 4;               // r0 in 0..15; rows r0, r0+16
    float acc0 = 0.f, acc1 = 0.f;
    #pragma unroll 8
    for (int k = 0; k < FILTERS; k += 4) {
        float4 h0 = *(const float4*)&Ht[r0][k];
        float4 h1 = *(const float4*)&Ht[r0 + 16][k];
        float w0 = W2s[k][c], w1 = W2s[k + 1][c];
        float w2 = W2s[k + 2][c], w3 = W2s[k + 3][c];
        acc0 = fmaf(h0.x, w0, acc0); acc0 = fmaf(h0.y, w1, acc0);
        acc0 = fmaf(h0.z, w2, acc0); acc0 = fmaf(h0.w, w3, acc0);
        acc1 = fmaf(h1.x, w0, acc1); acc1 = fmaf(h1.y, w1, acc1);
        acc1 = fmaf(h1.z, w2, acc1); acc1 = fmaf(h1.w, w3, acc1);
    }
    int gr0 = base + r0, gr1 = base + r0 + 16;
    if (gr0 < N_NODES) g_g[(size_t)gr0 * NCLS + c] = acc0;
    if (gr1 < N_NODES) g_g[(size_t)gr1 * NCLS + c] = acc1;
}

// ---------------- Propagate 2 + softmax: 16 threads/node ----------------
__global__ __launch_bounds__(256) void k_prop2(float* __restrict__ out) {
    int node = blockIdx.x * 16 + (threadIdx.x >> 4);
    int c = threadIdx.x & 15;
    int s = g_rowptr[node], e = g_rowptr[node + 1];
    float acc = 0.f;
    for (int i = s; i < e; i++)
        acc = fmaf(g_csw[i], g_g[(size_t)g_csrc[i] * NCLS + c], acc);
    float m = acc;
    #pragma unroll
    for (int off = 8; off; off >>= 1)
        m = fmaxf(m, __shfl_xor_sync(0xffffffffu, m, off, 16));
    float ex = __expf(acc - m);
    float sum = ex;
    #pragma unroll
    for (int off = 8; off; off >>= 1)
        sum += __shfl_xor_sync(0xffffffffu, sum, off, 16);
    out[(size_t)node * NCLS + c] = ex / sum;
}

// ---------------- launch ----------------
extern "C" void kernel_launch(void* const* d_in, const int* in_sizes, int n_in,
                              void* d_out, int out_size) {
    const float* x    = (const float*)d_in[0];
    const float* W1   = (const float*)d_in[1];
    const float* W2   = (const float*)d_in[2];
    const float* ew   = (const float*)d_in[3];
    const int*   esrc = (const int*)d_in[4];
    const int*   edst = (const int*)d_in[5];
    float* out = (float*)d_out;

    k_zero_deg<<<(N_NODES + 255) / 256, 256>>>();
    k_count   <<<(N_EDGES + 255) / 256, 256>>>(edst);
    k_scan    <<<1, 1024>>>();
    k_scatter <<<(N_EDGES + 255) / 256, 256>>>(esrc, edst, ew);

    dim3 g1((N_NODES + BM - 1) / BM, FILTERS / BN);
    k_gemm1<<<g1, 256>>>(x, W1);

    k_prop1<<<N_NODES / 4, 256>>>();
    k_gemm2<<<(N_NODES + 31) / 32, 256>>>(W2);
    k_prop2<<<N_NODES / 16, 256>>>(out);
}

// round 6
// speedup vs baseline: 1.2952x; 1.2952x over previous
#include <cuda_runtime.h>
#include <cuda_bf16.h>
#include <cstdint>
#include <cstddef>

#define N_NODES 50000
#define N_EDGES 1600000
#define D_FEAT  512
#define FILTERS 256
#define NCLS    16

// ---------------- device scratch (no allocations allowed) ----------------
__device__ __align__(16) float g_xw1[(size_t)N_NODES * FILTERS];   // X @ W1
__device__ __align__(16) float g_h  [(size_t)N_NODES * FILTERS];   // relu(A @ XW1)
__device__ __align__(16) float g_g  [(size_t)N_NODES * NCLS];      // H @ W2
__device__ int   g_deg[N_NODES];
__device__ int   g_rowptr[N_NODES + 1];
__device__ int   g_cursor[N_NODES];
__device__ int   g_csrc[N_EDGES];
__device__ float g_csw [N_EDGES];
// W1 in mma-fragment order: [term hi/lo][n_tile 32][kstep 32][lane 32] -> (b0,b1)
__device__ __align__(16) uint2 g_w1b[2][32][32][32];

__device__ __forceinline__ uint32_t pack_bf2(float a, float b) {
    __nv_bfloat162 p = __floats2bfloat162_rn(a, b);
    return *reinterpret_cast<uint32_t*>(&p);
}

__device__ __forceinline__ void mma16816(float* d, const uint32_t* a, const uint32_t* b) {
    asm volatile(
        "mma.sync.aligned.m16n8k16.row.col.f32.bf16.bf16.f32 "
        "{%0,%1,%2,%3}, {%4,%5,%6,%7}, {%8,%9}, {%0,%1,%2,%3};"
        : "+f"(d[0]), "+f"(d[1]), "+f"(d[2]), "+f"(d[3])
        : "r"(a[0]), "r"(a[1]), "r"(a[2]), "r"(a[3]), "r"(b[0]), "r"(b[1]));
}

// ---------------- CSR build ----------------
__global__ void k_zero_deg() {
    int i = blockIdx.x * 256 + threadIdx.x;
    if (i < N_NODES) g_deg[i] = 0;
}

__global__ void k_count(const int* __restrict__ dst) {
    int e = blockIdx.x * 256 + threadIdx.x;
    if (e < N_EDGES) atomicAdd(&g_deg[dst[e]], 1);
}

// Sequential-per-thread + hierarchical block scan (1024 threads, 1 block)
__global__ __launch_bounds__(1024) void k_scan() {
    __shared__ int wsum[32];
    const int PER = (N_NODES + 1023) / 1024;   // 49
    int t = threadIdx.x;
    int s = t * PER;
    int e = min(s + PER, N_NODES);
    if (s > e) s = e;
    int sum = 0;
    for (int i = s; i < e; i++) sum += g_deg[i];
    int lane = t & 31, w = t >> 5;
    int incl = sum;
    #pragma unroll
    for (int off = 1; off < 32; off <<= 1) {
        int v = __shfl_up_sync(0xffffffffu, incl, off);
        if (lane >= off) incl += v;
    }
    if (lane == 31) wsum[w] = incl;
    __syncthreads();
    if (w == 0) {
        int v = wsum[lane];
        int wi = v;
        #pragma unroll
        for (int off = 1; off < 32; off <<= 1) {
            int u = __shfl_up_sync(0xffffffffu, wi, off);
            if (lane >= off) wi += u;
        }
        wsum[lane] = wi - v;   // exclusive warp prefix
    }
    __syncthreads();
    int run = wsum[w] + incl - sum;    // exclusive prefix for this thread's segment
    for (int i = s; i < e; i++) {
        g_rowptr[i] = run;
        g_cursor[i] = run;
        run += g_deg[i];
    }
    if (e >= N_NODES) g_rowptr[N_NODES] = run;
}

__global__ void k_scatter(const int* __restrict__ src, const int* __restrict__ dst,
                          const float* __restrict__ w) {
    int e = blockIdx.x * 256 + threadIdx.x;
    if (e < N_EDGES) {
        int d = dst[e];
        int pos = atomicAdd(&g_cursor[d], 1);
        g_csrc[pos] = src[e];
        g_csw [pos] = w[e];
    }
}

// ---------------- W1 -> fragment-ordered bf16 hi/lo ----------------
// For mma.m16n8k16 .row.col, the B (col-major) fragment for lane l:
//   b0 = (k = kq, kq+1, n = l/4),  b1 = (k = kq+8, kq+9, n = l/4),  kq = (l%4)*2
__global__ void k_w1frag(const float* __restrict__ W1) {
    int i = blockIdx.x * 256 + threadIdx.x;    // 32 n_tiles * 32 ksteps * 32 lanes
    if (i >= 32 * 32 * 32) return;
    int l  = i & 31;
    int ks = (i >> 5) & 31;
    int nt = i >> 10;
    int n  = nt * 8 + (l >> 2);
    int k  = ks * 16 + (l & 3) * 2;
    float v00 = W1[(size_t)(k + 0) * FILTERS + n];
    float v01 = W1[(size_t)(k + 1) * FILTERS + n];
    float v10 = W1[(size_t)(k + 8) * FILTERS + n];
    float v11 = W1[(size_t)(k + 9) * FILTERS + n];
    float h00 = __bfloat162float(__float2bfloat16(v00));
    float h01 = __bfloat162float(__float2bfloat16(v01));
    float h10 = __bfloat162float(__float2bfloat16(v10));
    float h11 = __bfloat162float(__float2bfloat16(v11));
    g_w1b[0][nt][ks][l] = make_uint2(pack_bf2(v00, v01), pack_bf2(v10, v11));
    g_w1b[1][nt][ks][l] = make_uint2(pack_bf2(v00 - h00, v01 - h01),
                                     pack_bf2(v10 - h10, v11 - h11));
}

// ---------------- GEMM1 via HMMA (mma.sync bf16, hi/lo split) ----------------
// CTA tile 128(M) x 64(N), 8 warps as 4(M) x 2(N), warp tile 32x32.
// Per warp: Mfrags=2 (16 rows each), Nfrags=4 (8 cols each).
__global__ __launch_bounds__(256) void k_gemm1_mma(const float* __restrict__ X) {
    int t = threadIdx.x, w = t >> 5, l = t & 31;
    int wm = w >> 1, wn = w & 1;
    int bm = blockIdx.x * 128;
    int r_base = bm + wm * 32 + (l >> 2);      // + m*16, +8 for frag halves
    int qc = (l & 3) * 2;                      // quad col-pair base

    float d[2][4][4];
    #pragma unroll
    for (int m = 0; m < 2; m++)
        #pragma unroll
        for (int f = 0; f < 4; f++)
            #pragma unroll
            for (int j = 0; j < 4; j++) d[m][f][j] = 0.f;

    // clamped row indices (OOB rows compute garbage, discarded at store)
    int rr[2][2];
    #pragma unroll
    for (int m = 0; m < 2; m++) {
        rr[m][0] = min(r_base + m * 16,     N_NODES - 1);
        rr[m][1] = min(r_base + m * 16 + 8, N_NODES - 1);
    }
    int nt_base = blockIdx.y * 8 + wn * 4;

    #pragma unroll 4
    for (int ks = 0; ks < 32; ks++) {
        int k0 = ks * 16;
        uint32_t bhi[4][2], blo[4][2];
        #pragma unroll
        for (int f = 0; f < 4; f++) {
            uint2 vh = g_w1b[0][nt_base + f][ks][l];
            uint2 vl = g_w1b[1][nt_base + f][ks][l];
            bhi[f][0] = vh.x; bhi[f][1] = vh.y;
            blo[f][0] = vl.x; blo[f][1] = vl.y;
        }
        uint32_t ahi[2][4], alo[2][4];
        #pragma unroll
        for (int m = 0; m < 2; m++) {
            float2 p00 = *(const float2*)(X + (size_t)rr[m][0] * D_FEAT + k0 + qc);
            float2 p10 = *(const float2*)(X + (size_t)rr[m][1] * D_FEAT + k0 + qc);
            float2 p01 = *(const float2*)(X + (size_t)rr[m][0] * D_FEAT + k0 + qc + 8);
            float2 p11 = *(const float2*)(X + (size_t)rr[m][1] * D_FEAT + k0 + qc + 8);
            float h;
            ahi[m][0] = pack_bf2(p00.x, p00.y);
            ahi[m][1] = pack_bf2(p10.x, p10.y);
            ahi[m][2] = pack_bf2(p01.x, p01.y);
            ahi[m][3] = pack_bf2(p11.x, p11.y);
            float l00x, l00y, l10x, l10y, l01x, l01y, l11x, l11y;
            h = __bfloat162float(__float2bfloat16(p00.x)); l00x = p00.x - h;
            h = __bfloat162float(__float2bfloat16(p00.y)); l00y = p00.y - h;
            h = __bfloat162float(__float2bfloat16(p10.x)); l10x = p10.x - h;
            h = __bfloat162float(__float2bfloat16(p10.y)); l10y = p10.y - h;
            h = __bfloat162float(__float2bfloat16(p01.x)); l01x = p01.x - h;
            h = __bfloat162float(__float2bfloat16(p01.y)); l01y = p01.y - h;
            h = __bfloat162float(__float2bfloat16(p11.x)); l11x = p11.x - h;
            h = __bfloat162float(__float2bfloat16(p11.y)); l11y = p11.y - h;
            alo[m][0] = pack_bf2(l00x, l00y);
            alo[m][1] = pack_bf2(l10x, l10y);
            alo[m][2] = pack_bf2(l01x, l01y);
            alo[m][3] = pack_bf2(l11x, l11y);
        }
        #pragma unroll
        for (int m = 0; m < 2; m++)
            #pragma unroll
            for (int f = 0; f < 4; f++) {
                mma16816(d[m][f], ahi[m], bhi[f]);
                mma16816(d[m][f], ahi[m], blo[f]);
                mma16816(d[m][f], alo[m], bhi[f]);
            }
    }

    // epilogue: d0,d1 -> (r, n0..n0+1); d2,d3 -> (r+8, ...)
    int n_base = blockIdx.y * 64 + wn * 32;
    #pragma unroll
    for (int m = 0; m < 2; m++) {
        int r0 = r_base + m * 16;
        int r1 = r0 + 8;
        #pragma unroll
        for (int f = 0; f < 4; f++) {
            int n0 = n_base + f * 8 + qc;
            if (r0 < N_NODES)
                *(float2*)(g_xw1 + (size_t)r0 * FILTERS + n0) =
                    make_float2(d[m][f][0], d[m][f][1]);
            if (r1 < N_NODES)
                *(float2*)(g_xw1 + (size_t)r1 * FILTERS + n0) =
                    make_float2(d[m][f][2], d[m][f][3]);
        }
    }
}

// ---------------- Propagate 1 + relu: per-dst CSR, 64 threads/node, float4 ----------------
__global__ __launch_bounds__(256) void k_prop1() {
    int node = blockIdx.x * 4 + (threadIdx.x >> 6);
    int f = (threadIdx.x & 63) << 2;
    int s = g_rowptr[node], e = g_rowptr[node + 1];
    float4 acc = make_float4(0.f, 0.f, 0.f, 0.f);
    int i = s;
    for (; i + 1 < e; i += 2) {
        int   s0 = g_csrc[i],   s1 = g_csrc[i + 1];
        float w0 = g_csw[i],    w1 = g_csw[i + 1];
        float4 v0 = *(const float4*)(g_xw1 + (size_t)s0 * FILTERS + f);
        float4 v1 = *(const float4*)(g_xw1 + (size_t)s1 * FILTERS + f);
        acc.x = fmaf(w0, v0.x, acc.x); acc.y = fmaf(w0, v0.y, acc.y);
        acc.z = fmaf(w0, v0.z, acc.z); acc.w = fmaf(w0, v0.w, acc.w);
        acc.x = fmaf(w1, v1.x, acc.x); acc.y = fmaf(w1, v1.y, acc.y);
        acc.z = fmaf(w1, v1.z, acc.z); acc.w = fmaf(w1, v1.w, acc.w);
    }
    if (i < e) {
        int   s0 = g_csrc[i];
        float w0 = g_csw[i];
        float4 v0 = *(const float4*)(g_xw1 + (size_t)s0 * FILTERS + f);
        acc.x = fmaf(w0, v0.x, acc.x); acc.y = fmaf(w0, v0.y, acc.y);
        acc.z = fmaf(w0, v0.z, acc.z); acc.w = fmaf(w0, v0.w, acc.w);
    }
    float4 r = make_float4(fmaxf(acc.x, 0.f), fmaxf(acc.y, 0.f),
                           fmaxf(acc.z, 0.f), fmaxf(acc.w, 0.f));
    *(float4*)(g_h + (size_t)node * FILTERS + f) = r;
}

// ---------------- GEMM2: H[50000,256] @ W2[256,16] ----------------
__global__ __launch_bounds__(256) void k_gemm2(const float* __restrict__ W2) {
    __shared__ float Ht[32][FILTERS];
    __shared__ float W2s[FILTERS][NCLS];
    int t = threadIdx.x;
    #pragma unroll
    for (int i = 0; i < 16; i++)
        ((float*)W2s)[t + i * 256] = W2[t + i * 256];
    int base = blockIdx.x * 32;
    #pragma unroll
    for (int i = 0; i < 8; i++) {
        int idx = t + i * 256;
        int r = idx >> 6;
        int c4 = (idx & 63) << 2;
        int gr = base + r;
        float4 v = make_float4(0.f, 0.f, 0.f, 0.f);
        if (gr < N_NODES) v = *(const float4*)(g_h + (size_t)gr * FILTERS + c4);
        *(float4*)&Ht[r][c4] = v;
    }
    __syncthreads();
    int c = t & 15, r0 = t >> 4;
    float acc0 = 0.f, acc1 = 0.f;
    #pragma unroll 8
    for (int k = 0; k < FILTERS; k += 4) {
        float4 h0 = *(const float4*)&Ht[r0][k];
        float4 h1 = *(const float4*)&Ht[r0 + 16][k];
        float w0 = W2s[k][c], w1 = W2s[k + 1][c];
        float w2 = W2s[k + 2][c], w3 = W2s[k + 3][c];
        acc0 = fmaf(h0.x, w0, acc0); acc0 = fmaf(h0.y, w1, acc0);
        acc0 = fmaf(h0.z, w2, acc0); acc0 = fmaf(h0.w, w3, acc0);
        acc1 = fmaf(h1.x, w0, acc1); acc1 = fmaf(h1.y, w1, acc1);
        acc1 = fmaf(h1.z, w2, acc1); acc1 = fmaf(h1.w, w3, acc1);
    }
    int gr0 = base + r0, gr1 = base + r0 + 16;
    if (gr0 < N_NODES) g_g[(size_t)gr0 * NCLS + c] = acc0;
    if (gr1 < N_NODES) g_g[(size_t)gr1 * NCLS + c] = acc1;
}

// ---------------- Propagate 2 + softmax: 16 threads/node ----------------
__global__ __launch_bounds__(256) void k_prop2(float* __restrict__ out) {
    int node = blockIdx.x * 16 + (threadIdx.x >> 4);
    int c = threadIdx.x & 15;
    int s = g_rowptr[node], e = g_rowptr[node + 1];
    float acc = 0.f;
    for (int i = s; i < e; i++)
        acc = fmaf(g_csw[i], g_g[(size_t)g_csrc[i] * NCLS + c], acc);
    float m = acc;
    #pragma unroll
    for (int off = 8; off; off >>= 1)
        m = fmaxf(m, __shfl_xor_sync(0xffffffffu, m, off, 16));
    float ex = __expf(acc - m);
    float sum = ex;
    #pragma unroll
    for (int off = 8; off; off >>= 1)
        sum += __shfl_xor_sync(0xffffffffu, sum, off, 16);
    out[(size_t)node * NCLS + c] = ex / sum;
}

// ---------------- launch ----------------
extern "C" void kernel_launch(void* const* d_in, const int* in_sizes, int n_in,
                              void* d_out, int out_size) {
    const float* x    = (const float*)d_in[0];
    const float* W1   = (const float*)d_in[1];
    const float* W2   = (const float*)d_in[2];
    const float* ew   = (const float*)d_in[3];
    const int*   esrc = (const int*)d_in[4];
    const int*   edst = (const int*)d_in[5];
    float* out = (float*)d_out;

    k_w1frag  <<<(32 * 32 * 32 + 255) / 256, 256>>>(W1);
    k_zero_deg<<<(N_NODES + 255) / 256, 256>>>();
    k_count   <<<(N_EDGES + 255) / 256, 256>>>(edst);
    k_scan    <<<1, 1024>>>();
    k_scatter <<<(N_EDGES + 255) / 256, 256>>>(esrc, edst, ew);

    dim3 g1((N_NODES + 127) / 128, FILTERS / 64);
    k_gemm1_mma<<<g1, 256>>>(x);

    k_prop1<<<N_NODES / 4, 256>>>();
    k_gemm2<<<(N_NODES + 31) / 32, 256>>>(W2);
    k_prop2<<<N_NODES / 16, 256>>>(out);
}